// round 3
// baseline (speedup 1.0000x reference)
#include <cuda_runtime.h>
#include <cuda_bf16.h>

// Problem constants
#define B_    64
#define Lnum  2048
#define CHn   128
#define En    4
#define HIDn  64
#define OUTn  10
#define Kw    32
#define Tn    253          // (2048-32)/8 + 1
#define Mrows 320          // 256 expert rows (e*64+h) then 64 gate rows
#define Kdim  4096         // CH * Kw, ordered kw*128 + c

// GEMM tiling
#define BM 64
#define BN 128
#define KC 16
#define WP 68              // BM + 4 pad
#define PP 132             // BN + 4 pad

// Device scratch (no runtime allocation allowed)
__device__ float g_w2[Mrows * Kdim];     // 5.24 MB reordered weights [row][kw*128+c]
__device__ float g_bias[Mrows];
__device__ float g_gmax[B_ * Mrows];     // max(relu(conv+b)) over t, per (b, row)

// ---------------------------------------------------------------------------
// Prep: reorder conv weights, gather biases, zero the max scratch.
// ---------------------------------------------------------------------------
__global__ void prep_kernel(const float* __restrict__ gate_cw,
                            const float* __restrict__ gate_cb,
                            const float* __restrict__ exp_cw,
                            const float* __restrict__ exp_cb) {
    int idx = blockIdx.x * blockDim.x + threadIdx.x;
    if (idx < Mrows * Kdim) {
        int row = idx / Kdim;
        int k   = idx - row * Kdim;
        int kw  = k >> 7;        // k / 128
        int c   = k & 127;
        float v;
        if (row < 256) v = exp_cw[((size_t)row * CHn + c) * Kw + kw];   // [E*HID, CH, K]
        else           v = gate_cw[((size_t)(row - 256) * CHn + c) * Kw + kw];
        g_w2[idx] = v;
    }
    if (idx < Mrows)      g_bias[idx] = (idx < 256) ? exp_cb[idx] : gate_cb[idx - 256];
    if (idx < B_ * Mrows) g_gmax[idx] = 0.f;
}

// ---------------------------------------------------------------------------
// Fused implicit-GEMM conv (gate + experts) + bias + ReLU + max-over-t.
// C[320, B*253] = W[320, 4096] x Patches[4096, B*253]
// One block: 64 rows x 128 positions (one batch, one t-half).
// Smem: 2*(16*68 + 16*132)*4 = 25600 B  (< 48 KB static limit, 2 CTAs/SM)
// ---------------------------------------------------------------------------
__global__ __launch_bounds__(128) void conv_gemm(const float* __restrict__ fs,
                                                 const float* __restrict__ fp) {
    __shared__ __align__(16) float Ws[2][KC][WP];
    __shared__ __align__(16) float Ps[2][KC][PP];

    const int mt  = blockIdx.x;              // 0..4
    const int by  = blockIdx.y;              // 0..127
    const int b   = by >> 1;
    const int t0  = (by & 1) << 7;           // 0 or 128
    const int m0  = mt * BM;
    const int tid = threadIdx.x;
    const int tx  = tid & 15;                // 16 in N dir
    const int ty  = tid >> 4;                // 8  in M dir

    const float* fsb = fs + (size_t)b * Lnum * 64;
    const float* fpb = fp + (size_t)b * Lnum * 64;

    float acc[8][8];
#pragma unroll
    for (int i = 0; i < 8; i++)
#pragma unroll
        for (int j = 0; j < 8; j++) acc[i][j] = 0.f;

    float4 Wr[2], Pr[4];

    // chunk ci in [0,256): kw = ci>>3, channel-group cg = ci&7 (16 channels)
    auto load_g = [&](int ci) {
        const int kw = ci >> 3, cg = ci & 7;
        const int kbase = kw * 128 + cg * 16;
        // W: 64 rows x 16 k = 256 float4, 2 per thread. r = row, q in [0,4)
#pragma unroll
        for (int s = 0; s < 2; s++) {
            int v = tid + s * 128;
            int r = v >> 2, q = v & 3;
            Wr[s] = *reinterpret_cast<const float4*>(
                g_w2 + (size_t)(m0 + r) * Kdim + kbase + 4 * q);
        }
        // P: 128 t x 16 ch = 512 float4, 4 per thread.
        const float* src = (cg < 4) ? fsb : fpb;
        const int cb = (cg & 3) * 16;        // channel offset inside fs/fp (64-wide)
#pragma unroll
        for (int s = 0; s < 4; s++) {
            int v = tid + s * 128;
            int t = v >> 2, q = v & 3;
            int tg = t0 + t;
            if (tg < Tn) {
                int l = tg * 8 + kw;         // <= 2047 for valid t
                Pr[s] = *reinterpret_cast<const float4*>(src + (size_t)l * 64 + cb + 4 * q);
            } else {
                Pr[s] = make_float4(0.f, 0.f, 0.f, 0.f);
            }
        }
    };
    auto store_s = [&](int buf) {
#pragma unroll
        for (int s = 0; s < 2; s++) {
            int v = tid + s * 128;
            int r = v >> 2, q = v & 3;
            Ws[buf][4 * q + 0][r] = Wr[s].x;
            Ws[buf][4 * q + 1][r] = Wr[s].y;
            Ws[buf][4 * q + 2][r] = Wr[s].z;
            Ws[buf][4 * q + 3][r] = Wr[s].w;
        }
#pragma unroll
        for (int s = 0; s < 4; s++) {
            int v = tid + s * 128;
            int t = v >> 2, q = v & 3;
            Ps[buf][4 * q + 0][t] = Pr[s].x;
            Ps[buf][4 * q + 1][t] = Pr[s].y;
            Ps[buf][4 * q + 2][t] = Pr[s].z;
            Ps[buf][4 * q + 3][t] = Pr[s].w;
        }
    };

    load_g(0);
    store_s(0);
    __syncthreads();

    const int NCH = Kdim / KC;   // 256 chunks
    for (int ci = 0; ci < NCH; ci++) {
        const int cur = ci & 1;
        if (ci + 1 < NCH) load_g(ci + 1);
#pragma unroll
        for (int kk = 0; kk < KC; kk++) {
            float4 a0 = *reinterpret_cast<const float4*>(&Ws[cur][kk][ty * 8]);
            float4 a1 = *reinterpret_cast<const float4*>(&Ws[cur][kk][ty * 8 + 4]);
            float4 b0 = *reinterpret_cast<const float4*>(&Ps[cur][kk][tx * 8]);
            float4 b1 = *reinterpret_cast<const float4*>(&Ps[cur][kk][tx * 8 + 4]);
            float av[8] = {a0.x, a0.y, a0.z, a0.w, a1.x, a1.y, a1.z, a1.w};
            float bv[8] = {b0.x, b0.y, b0.z, b0.w, b1.x, b1.y, b1.z, b1.w};
#pragma unroll
            for (int i = 0; i < 8; i++)
#pragma unroll
                for (int j = 0; j < 8; j++)
                    acc[i][j] = fmaf(av[i], bv[j], acc[i][j]);
        }
        if (ci + 1 < NCH) store_s(cur ^ 1);
        __syncthreads();
    }

    // Epilogue: bias + relu + max over this block's t-range, atomicMax to scratch.
#pragma unroll
    for (int i = 0; i < 8; i++) {
        const int m = m0 + ty * 8 + i;
        const float bias = g_bias[m];
        float vmax = 0.f;
#pragma unroll
        for (int j = 0; j < 8; j++) {
            int tg = t0 + tx * 8 + j;
            if (tg < Tn) vmax = fmaxf(vmax, fmaxf(acc[i][j] + bias, 0.f));
        }
        // reduce across the 16 tx lanes (xor keeps lanes inside their 16-group)
#pragma unroll
        for (int off = 8; off > 0; off >>= 1)
            vmax = fmaxf(vmax, __shfl_xor_sync(0xffffffffu, vmax, off));
        if (tx == 0)
            atomicMax(reinterpret_cast<unsigned int*>(&g_gmax[b * Mrows + m]),
                      __float_as_uint(vmax));   // valid: all values >= 0
    }
}

// ---------------------------------------------------------------------------
// Tail: gate softmax, expert MLPs, mixing, fc + log-softmax. One block per b.
// ---------------------------------------------------------------------------
__global__ void tail_kernel(const float* __restrict__ gate_lw,
                            const float* __restrict__ gate_lb,
                            const float* __restrict__ exp_w1,
                            const float* __restrict__ exp_b1,
                            const float* __restrict__ exp_w2,
                            const float* __restrict__ exp_b2,
                            const float* __restrict__ fc_w,
                            const float* __restrict__ fc_b,
                            float* __restrict__ out,
                            int out_size) {
    const int b = blockIdx.x;
    const int tid = threadIdx.x;   // 64 threads

    __shared__ float sh_h[256];    // expert pooled [E*HID]
    __shared__ float sh_g[64];     // gate pooled
    __shared__ float gate_o[4];
    __shared__ float h1[128];      // [E*32]
    __shared__ float h2[64];       // [E*16]
    __shared__ float mixed[16];

    const float* gm = g_gmax + b * Mrows;
#pragma unroll
    for (int s = 0; s < 4; s++) sh_h[tid + s * 64] = gm[tid + s * 64];
    sh_g[tid] = gm[256 + tid];
    __syncthreads();

    if (tid < 4) {
        float s = gate_lb[tid];
        for (int h = 0; h < 64; h++) s += sh_g[h] * gate_lw[tid * 64 + h];
        gate_o[tid] = s;
    }
    __syncthreads();
    if (tid == 0) {
        float mx = fmaxf(fmaxf(gate_o[0], gate_o[1]), fmaxf(gate_o[2], gate_o[3]));
        float e0 = expf(gate_o[0] - mx), e1 = expf(gate_o[1] - mx);
        float e2 = expf(gate_o[2] - mx), e3 = expf(gate_o[3] - mx);
        float inv = 1.f / (e0 + e1 + e2 + e3);
        gate_o[0] = e0 * inv; gate_o[1] = e1 * inv;
        gate_o[2] = e2 * inv; gate_o[3] = e3 * inv;
    }
    __syncthreads();

    // h1 = relu(h @ w1^T + b1): 128 outputs
    for (int r = tid; r < 128; r += 64) {
        int e = r >> 5;
        float s = exp_b1[r];
        const float* w = exp_w1 + (size_t)r * 64;
        const float* hv = sh_h + e * 64;
        for (int c = 0; c < 64; c++) s += hv[c] * w[c];
        h1[r] = fmaxf(s, 0.f);
    }
    __syncthreads();

    // h2 = relu(h1 @ w2^T + b2): 64 outputs (one per thread)
    {
        int e = tid >> 4;
        float s = exp_b2[tid];
        const float* w = exp_w2 + (size_t)tid * 32;
        const float* hv = h1 + e * 32;
        for (int o = 0; o < 32; o++) s += hv[o] * w[o];
        h2[tid] = fmaxf(s, 0.f);
    }
    __syncthreads();

    if (tid < 16) {
        float s = 0.f;
        for (int e = 0; e < En; e++) s += gate_o[e] * h2[e * 16 + tid];
        mixed[tid] = s;
    }
    __syncthreads();

    if (tid == 0) {
        float lg[OUTn];
        float mx = -1e30f;
        for (int k = 0; k < OUTn; k++) {
            float s = fc_b[k];
            for (int f = 0; f < 16; f++) s += mixed[f] * fc_w[k * 16 + f];
            lg[k] = s;
            mx = fmaxf(mx, s);
        }
        float se = 0.f;
        for (int k = 0; k < OUTn; k++) se += expf(lg[k] - mx);
        float lse = mx + logf(se);
        for (int k = 0; k < OUTn; k++) out[b * OUTn + k] = lg[k] - lse;
        if (out_size >= B_ * OUTn + B_ * En) {
            for (int e = 0; e < En; e++) out[B_ * OUTn + b * En + e] = gate_o[e];
        }
    }
}

// ---------------------------------------------------------------------------
extern "C" void kernel_launch(void* const* d_in, const int* in_sizes, int n_in,
                              void* d_out, int out_size) {
    const float* fs      = (const float*)d_in[0];
    const float* fp      = (const float*)d_in[1];
    const float* gate_cw = (const float*)d_in[2];
    const float* gate_cb = (const float*)d_in[3];
    const float* gate_lw = (const float*)d_in[4];
    const float* gate_lb = (const float*)d_in[5];
    const float* exp_cw  = (const float*)d_in[6];
    const float* exp_cb  = (const float*)d_in[7];
    const float* exp_w1  = (const float*)d_in[8];
    const float* exp_b1  = (const float*)d_in[9];
    const float* exp_w2  = (const float*)d_in[10];
    const float* exp_b2  = (const float*)d_in[11];
    const float* fc_w    = (const float*)d_in[12];
    const float* fc_b    = (const float*)d_in[13];
    float* out = (float*)d_out;

    {
        int total = Mrows * Kdim;
        int threads = 256;
        int blocks = (total + threads - 1) / threads;
        prep_kernel<<<blocks, threads>>>(gate_cw, gate_cb, exp_cw, exp_cb);
    }
    {
        dim3 grid(Mrows / BM, B_ * 2);   // 5 x 128
        conv_gemm<<<grid, 128>>>(fs, fp);
    }
    tail_kernel<<<B_, 64>>>(gate_lw, gate_lb, exp_w1, exp_b1, exp_w2, exp_b2,
                            fc_w, fc_b, out, out_size);
}

// round 4
// speedup vs baseline: 1.5318x; 1.5318x over previous
#include <cuda_runtime.h>
#include <cuda_bf16.h>
#include <cstdint>

// Problem constants
#define B_    64
#define Lnum  2048
#define CHn   128
#define En    4
#define HIDn  64
#define OUTn  10
#define Kw    32
#define Tn    253          // (2048-32)/8 + 1
#define Mrows 320          // 256 expert rows then 64 gate rows
#define Kdim  4096         // CH * Kw, ordered kw*128 + c

// GEMM tiling
#define BM 64
#define BN 128
#define KC 16
#define NCH (Kdim / KC)    // 256 chunks: kw = ci>>3, cg = ci&7
#define SAS 24             // smem row stride (bf16 elems): 48B -> conflict-free
#define SBS 24

// Device scratch (no runtime allocation allowed)
__device__ uint16_t g_whi[Mrows * Kdim];      // bf16 hi of reordered W [row][kw*128+c]
__device__ uint16_t g_wlo[Mrows * Kdim];      // bf16 lo
__device__ uint16_t g_xhi[B_ * Lnum * CHn];   // bf16 hi of features [b][l][c]
__device__ uint16_t g_xlo[B_ * Lnum * CHn];   // bf16 lo
__device__ float    g_bias[Mrows];
__device__ float    g_gmax[B_ * Mrows];       // max(relu(conv+b)) over t

static __device__ __forceinline__ uint16_t bf_bits(float v) {
    return __bfloat16_as_ushort(__float2bfloat16(v));
}
static __device__ __forceinline__ void split_bf16(float v, uint16_t& hi, uint16_t& lo) {
    __nv_bfloat16 h = __float2bfloat16(v);
    hi = __bfloat16_as_ushort(h);
    lo = bf_bits(v - __bfloat162float(h));
}

// ---------------------------------------------------------------------------
// Prep W: reorder conv weights to [row][kw*128+c], split bf16 hi/lo.
// Also biases and zeroing of the max scratch.
// ---------------------------------------------------------------------------
__global__ void prep_w(const float* __restrict__ gate_cw,
                       const float* __restrict__ gate_cb,
                       const float* __restrict__ exp_cw,
                       const float* __restrict__ exp_cb) {
    int idx = blockIdx.x * blockDim.x + threadIdx.x;
    if (idx < Mrows * Kdim) {
        int row = idx / Kdim;
        int k   = idx - row * Kdim;
        int kw  = k >> 7;
        int c   = k & 127;
        float v;
        if (row < 256) v = exp_cw[((size_t)row * CHn + c) * Kw + kw];
        else           v = gate_cw[((size_t)(row - 256) * CHn + c) * Kw + kw];
        uint16_t h, l;
        split_bf16(v, h, l);
        g_whi[idx] = h;
        g_wlo[idx] = l;
    }
    if (idx < Mrows)      g_bias[idx] = (idx < 256) ? exp_cb[idx] : gate_cb[idx - 256];
    if (idx < B_ * Mrows) g_gmax[idx] = 0.f;
}

// ---------------------------------------------------------------------------
// Prep X: concat fs|fp channels -> [b][l][128], split bf16 hi/lo. float4 lanes.
// ---------------------------------------------------------------------------
__global__ void prep_x(const float* __restrict__ fs,
                       const float* __restrict__ fp) {
    int idx = blockIdx.x * blockDim.x + threadIdx.x;   // over B*L*32 float4 units
    if (idx >= B_ * Lnum * 32) return;
    int bl = idx >> 5;          // b*2048 + l
    int c4 = idx & 31;
    int c  = c4 * 4;
    const float* src = (c < 64) ? (fs + (size_t)bl * 64 + c)
                                : (fp + (size_t)bl * 64 + (c - 64));
    float4 v = *reinterpret_cast<const float4*>(src);
    uint16_t h0, l0, h1, l1, h2, l2, h3, l3;
    split_bf16(v.x, h0, l0); split_bf16(v.y, h1, l1);
    split_bf16(v.z, h2, l2); split_bf16(v.w, h3, l3);
    size_t base = (size_t)bl * CHn + c;
    uint2 hv, lv;
    hv.x = (uint32_t)h0 | ((uint32_t)h1 << 16);
    hv.y = (uint32_t)h2 | ((uint32_t)h3 << 16);
    lv.x = (uint32_t)l0 | ((uint32_t)l1 << 16);
    lv.y = (uint32_t)l2 | ((uint32_t)l3 << 16);
    *reinterpret_cast<uint2*>(g_xhi + base) = hv;
    *reinterpret_cast<uint2*>(g_xlo + base) = lv;
}

// ---------------------------------------------------------------------------
// bf16 m16n8k16 mma (fp32 accum)
// ---------------------------------------------------------------------------
static __device__ __forceinline__ void mma16816(float& c0, float& c1, float& c2, float& c3,
                                                uint32_t a0, uint32_t a1, uint32_t a2, uint32_t a3,
                                                uint32_t b0, uint32_t b1) {
    asm volatile(
        "mma.sync.aligned.m16n8k16.row.col.f32.bf16.bf16.f32 "
        "{%0,%1,%2,%3}, {%4,%5,%6,%7}, {%8,%9}, {%0,%1,%2,%3};\n"
        : "+f"(c0), "+f"(c1), "+f"(c2), "+f"(c3)
        : "r"(a0), "r"(a1), "r"(a2), "r"(a3), "r"(b0), "r"(b1));
}

// ---------------------------------------------------------------------------
// Fused conv-GEMM on tensor cores, split-bf16 3-term for fp32-class accuracy.
// C[320, B*253] = W[320,4096] x P[4096, B*253]; epilogue bias+relu+max-pool.
// Block: 64 rows x 128 t-positions (one batch, one t-half). 4 warps, 64x32 each.
// Smem: 36864B (double-buffered bf16 hi/lo tiles).
// ---------------------------------------------------------------------------
__global__ __launch_bounds__(128) void conv_gemm(int dummy) {
    __shared__ __align__(16) uint16_t sA[2][2][BM * SAS];   // [buf][hi/lo][m*24+k]
    __shared__ __align__(16) uint16_t sB[2][2][BN * SBS];   // [buf][hi/lo][t*24+k]

    const int mt  = blockIdx.x;              // 0..4
    const int by  = blockIdx.y;              // 0..127
    const int b   = by >> 1;
    const int t0  = (by & 1) << 7;           // 0 or 128
    const int m0  = mt * BM;
    const int tid  = threadIdx.x;
    const int wid  = tid >> 5;
    const int lane = tid & 31;
    const int g    = lane >> 2;              // row-in-frag group 0..7
    const int q    = lane & 3;               // quad col 0..3

    float acc[4][4][4];
#pragma unroll
    for (int mi = 0; mi < 4; mi++)
#pragma unroll
        for (int ni = 0; ni < 4; ni++)
#pragma unroll
            for (int r = 0; r < 4; r++) acc[mi][ni][r] = 0.f;

    // Staging regs for next-chunk globals
    uint4 stAh, stAl, stBh[2], stBl[2];
    const int rA = tid >> 1, hA = tid & 1;   // A: 64 rows x 2 16B-halves

    auto load_g = [&](int ci) {
        const int kw = ci >> 3, cg = ci & 7;
        const size_t kbase = (size_t)kw * 128 + cg * 16;
        {
            size_t off = (size_t)(m0 + rA) * Kdim + kbase + hA * 8;
            stAh = *reinterpret_cast<const uint4*>(g_whi + off);
            stAl = *reinterpret_cast<const uint4*>(g_wlo + off);
        }
#pragma unroll
        for (int s = 0; s < 2; s++) {
            int v = tid + s * 128;
            int t = v >> 1, h = v & 1;
            int tg = t0 + t;
            if (tg < Tn) {
                int l = tg * 8 + kw;
                size_t off = ((size_t)b * Lnum + l) * CHn + cg * 16 + h * 8;
                stBh[s] = *reinterpret_cast<const uint4*>(g_xhi + off);
                stBl[s] = *reinterpret_cast<const uint4*>(g_xlo + off);
            } else {
                stBh[s] = make_uint4(0, 0, 0, 0);
                stBl[s] = make_uint4(0, 0, 0, 0);
            }
        }
    };
    auto store_s = [&](int buf) {
        *reinterpret_cast<uint4*>(&sA[buf][0][rA * SAS + hA * 8]) = stAh;
        *reinterpret_cast<uint4*>(&sA[buf][1][rA * SAS + hA * 8]) = stAl;
#pragma unroll
        for (int s = 0; s < 2; s++) {
            int v = tid + s * 128;
            int t = v >> 1, h = v & 1;
            *reinterpret_cast<uint4*>(&sB[buf][0][t * SBS + h * 8]) = stBh[s];
            *reinterpret_cast<uint4*>(&sB[buf][1][t * SBS + h * 8]) = stBl[s];
        }
    };

    load_g(0);
    store_s(0);
    __syncthreads();

    for (int ci = 0; ci < NCH; ci++) {
        const int cur = ci & 1;
        if (ci + 1 < NCH) load_g(ci + 1);

        // Load fragments (conflict-free: 48B row stride)
        uint32_t ah[4][4], al[4][4], bh[4][2], bl[4][2];
        const uint16_t* pAh = sA[cur][0];
        const uint16_t* pAl = sA[cur][1];
        const uint16_t* pBh = sB[cur][0];
        const uint16_t* pBl = sB[cur][1];
#pragma unroll
        for (int mi = 0; mi < 4; mi++) {
            int r0 = (mi * 16 + g) * SAS;
            int r1 = (mi * 16 + g + 8) * SAS;
            ah[mi][0] = *reinterpret_cast<const uint32_t*>(pAh + r0 + 2 * q);
            ah[mi][1] = *reinterpret_cast<const uint32_t*>(pAh + r1 + 2 * q);
            ah[mi][2] = *reinterpret_cast<const uint32_t*>(pAh + r0 + 2 * q + 8);
            ah[mi][3] = *reinterpret_cast<const uint32_t*>(pAh + r1 + 2 * q + 8);
            al[mi][0] = *reinterpret_cast<const uint32_t*>(pAl + r0 + 2 * q);
            al[mi][1] = *reinterpret_cast<const uint32_t*>(pAl + r1 + 2 * q);
            al[mi][2] = *reinterpret_cast<const uint32_t*>(pAl + r0 + 2 * q + 8);
            al[mi][3] = *reinterpret_cast<const uint32_t*>(pAl + r1 + 2 * q + 8);
        }
#pragma unroll
        for (int ni = 0; ni < 4; ni++) {
            int nr = (wid * 32 + ni * 8 + g) * SBS;
            bh[ni][0] = *reinterpret_cast<const uint32_t*>(pBh + nr + 2 * q);
            bh[ni][1] = *reinterpret_cast<const uint32_t*>(pBh + nr + 2 * q + 8);
            bl[ni][0] = *reinterpret_cast<const uint32_t*>(pBl + nr + 2 * q);
            bl[ni][1] = *reinterpret_cast<const uint32_t*>(pBl + nr + 2 * q + 8);
        }

        // 3-term split-bf16: hi*hi + hi*lo + lo*hi
#pragma unroll
        for (int mi = 0; mi < 4; mi++)
#pragma unroll
            for (int ni = 0; ni < 4; ni++)
                mma16816(acc[mi][ni][0], acc[mi][ni][1], acc[mi][ni][2], acc[mi][ni][3],
                         ah[mi][0], ah[mi][1], ah[mi][2], ah[mi][3],
                         bh[ni][0], bh[ni][1]);
#pragma unroll
        for (int mi = 0; mi < 4; mi++)
#pragma unroll
            for (int ni = 0; ni < 4; ni++)
                mma16816(acc[mi][ni][0], acc[mi][ni][1], acc[mi][ni][2], acc[mi][ni][3],
                         ah[mi][0], ah[mi][1], ah[mi][2], ah[mi][3],
                         bl[ni][0], bl[ni][1]);
#pragma unroll
        for (int mi = 0; mi < 4; mi++)
#pragma unroll
            for (int ni = 0; ni < 4; ni++)
                mma16816(acc[mi][ni][0], acc[mi][ni][1], acc[mi][ni][2], acc[mi][ni][3],
                         al[mi][0], al[mi][1], al[mi][2], al[mi][3],
                         bh[ni][0], bh[ni][1]);

        __syncthreads();
        if (ci + 1 < NCH) {
            store_s(cur ^ 1);
            __syncthreads();
        }
    }

    // Epilogue: bias + relu + max over t, quad-reduce, atomicMax.
#pragma unroll
    for (int mi = 0; mi < 4; mi++) {
        const int row0 = m0 + mi * 16 + g;
        const float bias0 = g_bias[row0];
        const float bias1 = g_bias[row0 + 8];
        float v0 = 0.f, v1 = 0.f;
#pragma unroll
        for (int ni = 0; ni < 4; ni++) {
            int ncol = wid * 32 + ni * 8 + 2 * q;
            int tg0 = t0 + ncol;
            if (tg0 < Tn) {
                v0 = fmaxf(v0, fmaxf(acc[mi][ni][0] + bias0, 0.f));
                v1 = fmaxf(v1, fmaxf(acc[mi][ni][2] + bias1, 0.f));
            }
            if (tg0 + 1 < Tn) {
                v0 = fmaxf(v0, fmaxf(acc[mi][ni][1] + bias0, 0.f));
                v1 = fmaxf(v1, fmaxf(acc[mi][ni][3] + bias1, 0.f));
            }
        }
#pragma unroll
        for (int off = 1; off <= 2; off <<= 1) {
            v0 = fmaxf(v0, __shfl_xor_sync(0xffffffffu, v0, off));
            v1 = fmaxf(v1, __shfl_xor_sync(0xffffffffu, v1, off));
        }
        if (q == 0) {
            atomicMax(reinterpret_cast<unsigned int*>(&g_gmax[b * Mrows + row0]),
                      __float_as_uint(v0));
            atomicMax(reinterpret_cast<unsigned int*>(&g_gmax[b * Mrows + row0 + 8]),
                      __float_as_uint(v1));
        }
    }
}

// ---------------------------------------------------------------------------
// Tail: gate softmax, expert MLPs, mixing, fc + log-softmax. One block per b.
// ---------------------------------------------------------------------------
__global__ void tail_kernel(const float* __restrict__ gate_lw,
                            const float* __restrict__ gate_lb,
                            const float* __restrict__ exp_w1,
                            const float* __restrict__ exp_b1,
                            const float* __restrict__ exp_w2,
                            const float* __restrict__ exp_b2,
                            const float* __restrict__ fc_w,
                            const float* __restrict__ fc_b,
                            float* __restrict__ out,
                            int out_size) {
    const int b = blockIdx.x;
    const int tid = threadIdx.x;   // 64 threads

    __shared__ float sh_h[256];
    __shared__ float sh_g[64];
    __shared__ float gate_o[4];
    __shared__ float h1[128];
    __shared__ float h2[64];
    __shared__ float mixed[16];

    const float* gm = g_gmax + b * Mrows;
#pragma unroll
    for (int s = 0; s < 4; s++) sh_h[tid + s * 64] = gm[tid + s * 64];
    sh_g[tid] = gm[256 + tid];
    __syncthreads();

    if (tid < 4) {
        float s = gate_lb[tid];
        for (int h = 0; h < 64; h++) s += sh_g[h] * gate_lw[tid * 64 + h];
        gate_o[tid] = s;
    }
    __syncthreads();
    if (tid == 0) {
        float mx = fmaxf(fmaxf(gate_o[0], gate_o[1]), fmaxf(gate_o[2], gate_o[3]));
        float e0 = expf(gate_o[0] - mx), e1 = expf(gate_o[1] - mx);
        float e2 = expf(gate_o[2] - mx), e3 = expf(gate_o[3] - mx);
        float inv = 1.f / (e0 + e1 + e2 + e3);
        gate_o[0] = e0 * inv; gate_o[1] = e1 * inv;
        gate_o[2] = e2 * inv; gate_o[3] = e3 * inv;
    }
    __syncthreads();

    for (int r = tid; r < 128; r += 64) {
        int e = r >> 5;
        float s = exp_b1[r];
        const float* w = exp_w1 + (size_t)r * 64;
        const float* hv = sh_h + e * 64;
        for (int c = 0; c < 64; c++) s += hv[c] * w[c];
        h1[r] = fmaxf(s, 0.f);
    }
    __syncthreads();

    {
        int e = tid >> 4;
        float s = exp_b2[tid];
        const float* w = exp_w2 + (size_t)tid * 32;
        const float* hv = h1 + e * 32;
        for (int o = 0; o < 32; o++) s += hv[o] * w[o];
        h2[tid] = fmaxf(s, 0.f);
    }
    __syncthreads();

    if (tid < 16) {
        float s = 0.f;
        for (int e = 0; e < En; e++) s += gate_o[e] * h2[e * 16 + tid];
        mixed[tid] = s;
    }
    __syncthreads();

    if (tid == 0) {
        float lg[OUTn];
        float mx = -1e30f;
        for (int k = 0; k < OUTn; k++) {
            float s = fc_b[k];
            for (int f = 0; f < 16; f++) s += mixed[f] * fc_w[k * 16 + f];
            lg[k] = s;
            mx = fmaxf(mx, s);
        }
        float se = 0.f;
        for (int k = 0; k < OUTn; k++) se += expf(lg[k] - mx);
        float lse = mx + logf(se);
        for (int k = 0; k < OUTn; k++) out[b * OUTn + k] = lg[k] - lse;
        if (out_size >= B_ * OUTn + B_ * En) {
            for (int e = 0; e < En; e++) out[B_ * OUTn + b * En + e] = gate_o[e];
        }
    }
}

// ---------------------------------------------------------------------------
extern "C" void kernel_launch(void* const* d_in, const int* in_sizes, int n_in,
                              void* d_out, int out_size) {
    const float* fs      = (const float*)d_in[0];
    const float* fp      = (const float*)d_in[1];
    const float* gate_cw = (const float*)d_in[2];
    const float* gate_cb = (const float*)d_in[3];
    const float* gate_lw = (const float*)d_in[4];
    const float* gate_lb = (const float*)d_in[5];
    const float* exp_cw  = (const float*)d_in[6];
    const float* exp_cb  = (const float*)d_in[7];
    const float* exp_w1  = (const float*)d_in[8];
    const float* exp_b1  = (const float*)d_in[9];
    const float* exp_w2  = (const float*)d_in[10];
    const float* exp_b2  = (const float*)d_in[11];
    const float* fc_w    = (const float*)d_in[12];
    const float* fc_b    = (const float*)d_in[13];
    float* out = (float*)d_out;

    {
        int total = Mrows * Kdim;
        prep_w<<<(total + 255) / 256, 256>>>(gate_cw, gate_cb, exp_cw, exp_cb);
    }
    {
        int total = B_ * Lnum * 32;
        prep_x<<<(total + 255) / 256, 256>>>(fs, fp);
    }
    {
        dim3 grid(Mrows / BM, B_ * 2);   // 5 x 128
        conv_gemm<<<grid, 128>>>(0);
    }
    tail_kernel<<<B_, 64>>>(gate_lw, gate_lb, exp_w1, exp_b1, exp_w2, exp_b2,
                            fc_w, fc_b, out, out_size);
}

// round 6
// speedup vs baseline: 1.9447x; 1.2696x over previous
#include <cuda_runtime.h>
#include <cuda_bf16.h>
#include <cstdint>

// Problem constants
#define B_    64
#define Lnum  2048
#define CHn   128
#define En    4
#define OUTn  10
#define Tn    253
#define Mrows 320          // 256 expert rows then 64 gate rows
#define Kdim  4096         // CH * Kw, ordered kw*128 + c

// GEMM tiling: BM=64, BN=128, KC=32, 256 threads, warp grid 2x4 (tile 32x32)
#define KC     32
#define NCH    (Kdim / KC)        // 128 chunks: kw = ci>>2, cg = ci&3
#define BM     64
#define BN     128
#define PITCHB 80                 // bytes per smem row (64 data + 16 pad)
#define A_SZ   (BM * PITCHB)      // 5120
#define B_SZ   (BN * PITCHB)      // 10240
#define STG    (2*A_SZ + 2*B_SZ)  // 30720: [Ahi][Alo][Bhi][Blo]
#define OFF_AH 0
#define OFF_AL A_SZ
#define OFF_BH (2*A_SZ)
#define OFF_BL (2*A_SZ + B_SZ)
#define NSTAGE 4
#define DYN_SMEM (NSTAGE * STG)   // 122880

// Device scratch
__device__ __align__(256) uint16_t g_whi[Mrows * Kdim];
__device__ __align__(256) uint16_t g_wlo[Mrows * Kdim];
__device__ __align__(256) uint16_t g_xhi[B_ * Lnum * CHn];
__device__ __align__(256) uint16_t g_xlo[B_ * Lnum * CHn];
__device__ float g_bias[Mrows];
__device__ float g_gmax[B_ * Mrows];

// ------------------------------ PTX helpers -------------------------------
static __device__ __forceinline__ uint32_t smem_u32(const void* p) {
    uint32_t r;
    asm("{ .reg .u64 t; cvta.to.shared.u64 t, %1; cvt.u32.u64 %0, t; }"
        : "=r"(r) : "l"(p));
    return r;
}
#define CP16(dst, src) \
    asm volatile("cp.async.cg.shared.global [%0], [%1], 16;" \
                 :: "r"(dst), "l"(src) : "memory")
#define CP16Z(dst, src, sz) \
    asm volatile("cp.async.cg.shared.global [%0], [%1], 16, %2;" \
                 :: "r"(dst), "l"(src), "r"(sz) : "memory")
#define CP_COMMIT() asm volatile("cp.async.commit_group;" ::: "memory")
#define CP_WAIT(n)  asm volatile("cp.async.wait_group %0;" :: "n"(n) : "memory")

#define LDSM_X4(r, addr) \
    asm volatile("ldmatrix.sync.aligned.m8n8.x4.shared.b16 {%0,%1,%2,%3}, [%4];" \
        : "=r"((r)[0]), "=r"((r)[1]), "=r"((r)[2]), "=r"((r)[3]) : "r"(addr))

static __device__ __forceinline__ void mma16816(float& c0, float& c1, float& c2, float& c3,
                                                uint32_t a0, uint32_t a1, uint32_t a2, uint32_t a3,
                                                uint32_t b0, uint32_t b1) {
    asm volatile(
        "mma.sync.aligned.m16n8k16.row.col.f32.bf16.bf16.f32 "
        "{%0,%1,%2,%3}, {%4,%5,%6,%7}, {%8,%9}, {%0,%1,%2,%3};\n"
        : "+f"(c0), "+f"(c1), "+f"(c2), "+f"(c3)
        : "r"(a0), "r"(a1), "r"(a2), "r"(a3), "r"(b0), "r"(b1));
}

// ------------------------------ prep kernels ------------------------------
static __device__ __forceinline__ void split_bf16(float v, uint16_t& hi, uint16_t& lo) {
    __nv_bfloat16 h = __float2bfloat16(v);
    hi = __bfloat16_as_ushort(h);
    lo = __bfloat16_as_ushort(__float2bfloat16(v - __bfloat162float(h)));
}

__global__ void prep_w(const float* __restrict__ gate_cw,
                       const float* __restrict__ gate_cb,
                       const float* __restrict__ exp_cw,
                       const float* __restrict__ exp_cb) {
    int idx = blockIdx.x * blockDim.x + threadIdx.x;
    if (idx < Mrows * Kdim) {
        int row = idx / Kdim;
        int k   = idx - row * Kdim;
        int kw  = k >> 7;
        int c   = k & 127;
        float v;
        if (row < 256) v = exp_cw[((size_t)row * CHn + c) * 32 + kw];
        else           v = gate_cw[((size_t)(row - 256) * CHn + c) * 32 + kw];
        uint16_t h, l;
        split_bf16(v, h, l);
        g_whi[idx] = h;
        g_wlo[idx] = l;
    }
    if (idx < Mrows)      g_bias[idx] = (idx < 256) ? exp_cb[idx] : gate_cb[idx - 256];
    if (idx < B_ * Mrows) g_gmax[idx] = 0.f;
}

__global__ void prep_x(const float* __restrict__ fs,
                       const float* __restrict__ fp) {
    int idx = blockIdx.x * blockDim.x + threadIdx.x;   // B*L*32 float4 units
    if (idx >= B_ * Lnum * 32) return;
    int bl = idx >> 5;
    int c  = (idx & 31) * 4;
    const float* src = (c < 64) ? (fs + (size_t)bl * 64 + c)
                                : (fp + (size_t)bl * 64 + (c - 64));
    float4 v = *reinterpret_cast<const float4*>(src);
    uint16_t h0, l0, h1, l1, h2, l2, h3, l3;
    split_bf16(v.x, h0, l0); split_bf16(v.y, h1, l1);
    split_bf16(v.z, h2, l2); split_bf16(v.w, h3, l3);
    size_t base = (size_t)bl * CHn + c;
    uint2 hv, lv;
    hv.x = (uint32_t)h0 | ((uint32_t)h1 << 16);
    hv.y = (uint32_t)h2 | ((uint32_t)h3 << 16);
    lv.x = (uint32_t)l0 | ((uint32_t)l1 << 16);
    lv.y = (uint32_t)l2 | ((uint32_t)l3 << 16);
    *reinterpret_cast<uint2*>(g_xhi + base) = hv;
    *reinterpret_cast<uint2*>(g_xlo + base) = lv;
}

// --------------------- pipelined mma.sync conv GEMM -----------------------
// C[320, B*253] = W[320,4096] x P[4096, B*253], split-bf16 3 terms.
// Block 64x128 (one M-tile x one t-half of one batch). 4-stage cp.async.
__global__ __launch_bounds__(256) void conv_gemm() {
    extern __shared__ __align__(16) uint8_t sm[];
    const uint32_t base = smem_u32(sm);

    const int tid  = threadIdx.x;
    const int wid  = tid >> 5;
    const int lane = tid & 31;
    const int wm   = wid >> 2;            // 0..1  (M warp)
    const int wn   = wid & 3;             // 0..3  (N warp)
    const int g    = lane >> 2;
    const int q    = lane & 3;
    const int m0   = blockIdx.x * BM;
    const int bb   = blockIdx.y >> 1;
    const int t0   = (blockIdx.y & 1) << 7;

    // cp.async per-thread roles
    const int arow = tid >> 2, aq = tid & 3;     // A: 64 rows x 4 chunks

    // ldmatrix per-lane address components
    const int a_r = lane & 15;                   // row within m16 block
    const int a_c = (lane >> 4) << 4;            // +0/+16 bytes (k half)
    const int b_n = (lane & 7) | ((lane & 16) >> 1);  // 0..15 within n16 block
    const int b_c = (lane & 8) << 1;             // +0/+16 bytes (k half)

    float acc[2][4][4];
#pragma unroll
    for (int mb = 0; mb < 2; mb++)
#pragma unroll
        for (int nb = 0; nb < 4; nb++)
#pragma unroll
            for (int r = 0; r < 4; r++) acc[mb][nb][r] = 0.f;

    auto issue = [&](int ci) {
        if (ci >= NCH) return;
        const int kw = ci >> 2, cg = ci & 3;
        const uint32_t sb = base + (uint32_t)(ci & (NSTAGE - 1)) * STG;
        {   // A = W tile: 64 rows x 64B
            size_t go = (size_t)(m0 + arow) * Kdim + kw * 128 + cg * 32 + aq * 8;
            uint32_t so = sb + (uint32_t)(arow * PITCHB + aq * 16);
            CP16(so + OFF_AH, g_whi + go);
            CP16(so + OFF_AL, g_wlo + go);
        }
#pragma unroll
        for (int s = 0; s < 2; s++) {   // B = patches: 128 rows x 64B
            int v = tid + s * 256;
            int row = v >> 2, bq = v & 3;
            int t = t0 + row;
            unsigned sz = (t < Tn) ? 16u : 0u;
            int l = t * 8 + kw;
            size_t go = ((size_t)bb * Lnum + l) * CHn + cg * 32 + bq * 8;
            uint32_t so = sb + (uint32_t)(row * PITCHB + bq * 16);
            CP16Z(so + OFF_BH, g_xhi + go, sz);
            CP16Z(so + OFF_BL, g_xlo + go, sz);
        }
        CP_COMMIT();
    };

    issue(0); issue(1); issue(2);   // prologue: NSTAGE-1 stages in flight

    for (int ci = 0; ci < NCH; ci++) {
        CP_WAIT(2);                 // stage ci complete
        __syncthreads();            // visible to all warps; prev buf free
        issue(ci + 3);              // refill buf (ci+3)%4 (consumed at ci-1)

        const uint32_t sb = base + (uint32_t)(ci & (NSTAGE - 1)) * STG;
        const uint32_t aoff = sb + (uint32_t)((wm * 32 + a_r) * PITCHB + a_c);
        const uint32_t boff = sb + (uint32_t)((wn * 32 + b_n) * PITCHB + b_c);

#pragma unroll
        for (int ks = 0; ks < 2; ks++) {
            uint32_t ah[2][4], al[2][4], bh[8], bl[8];
            const uint32_t ko = ks * 32;
#pragma unroll
            for (int mb = 0; mb < 2; mb++) {
                LDSM_X4(ah[mb], aoff + OFF_AH + mb * (16 * PITCHB) + ko);
                LDSM_X4(al[mb], aoff + OFF_AL + mb * (16 * PITCHB) + ko);
            }
            LDSM_X4(bh,     boff + OFF_BH + ko);
            LDSM_X4(bh + 4, boff + OFF_BH + 16 * PITCHB + ko);
            LDSM_X4(bl,     boff + OFF_BL + ko);
            LDSM_X4(bl + 4, boff + OFF_BL + 16 * PITCHB + ko);

#pragma unroll
            for (int mb = 0; mb < 2; mb++)
#pragma unroll
                for (int nb = 0; nb < 4; nb++) {
                    float* c = acc[mb][nb];
                    mma16816(c[0], c[1], c[2], c[3],
                             ah[mb][0], ah[mb][1], ah[mb][2], ah[mb][3],
                             bh[2 * nb], bh[2 * nb + 1]);
                    mma16816(c[0], c[1], c[2], c[3],
                             ah[mb][0], ah[mb][1], ah[mb][2], ah[mb][3],
                             bl[2 * nb], bl[2 * nb + 1]);
                    mma16816(c[0], c[1], c[2], c[3],
                             al[mb][0], al[mb][1], al[mb][2], al[mb][3],
                             bh[2 * nb], bh[2 * nb + 1]);
                }
        }
    }

    // Epilogue: bias + relu + max over valid t, quad-reduce, atomicMax.
#pragma unroll
    for (int mb = 0; mb < 2; mb++) {
        const int row0 = m0 + wm * 32 + mb * 16 + g;
        const int row1 = row0 + 8;
        const float b0 = g_bias[row0];
        const float b1 = g_bias[row1];
        float v0 = 0.f, v1 = 0.f;
#pragma unroll
        for (int nb = 0; nb < 4; nb++) {
            int n = wn * 32 + nb * 8 + 2 * q;
            int tg = t0 + n;
            if (tg < Tn) {
                v0 = fmaxf(v0, fmaxf(acc[mb][nb][0] + b0, 0.f));
                v1 = fmaxf(v1, fmaxf(acc[mb][nb][2] + b1, 0.f));
            }
            if (tg + 1 < Tn) {
                v0 = fmaxf(v0, fmaxf(acc[mb][nb][1] + b0, 0.f));
                v1 = fmaxf(v1, fmaxf(acc[mb][nb][3] + b1, 0.f));
            }
        }
#pragma unroll
        for (int off = 1; off <= 2; off <<= 1) {
            v0 = fmaxf(v0, __shfl_xor_sync(0xffffffffu, v0, off));
            v1 = fmaxf(v1, __shfl_xor_sync(0xffffffffu, v1, off));
        }
        if (q == 0) {
            atomicMax(reinterpret_cast<unsigned int*>(&g_gmax[bb * Mrows + row0]),
                      __float_as_uint(v0));
            atomicMax(reinterpret_cast<unsigned int*>(&g_gmax[bb * Mrows + row1]),
                      __float_as_uint(v1));
        }
    }
}

// ------------------------------- tail -------------------------------------
__global__ void tail_kernel(const float* __restrict__ gate_lw,
                            const float* __restrict__ gate_lb,
                            const float* __restrict__ exp_w1,
                            const float* __restrict__ exp_b1,
                            const float* __restrict__ exp_w2,
                            const float* __restrict__ exp_b2,
                            const float* __restrict__ fc_w,
                            const float* __restrict__ fc_b,
                            float* __restrict__ out,
                            int out_size) {
    const int b = blockIdx.x;
    const int tid = threadIdx.x;   // 64 threads

    __shared__ float sh_h[256];
    __shared__ float sh_g[64];
    __shared__ float gate_o[4];
    __shared__ float h1[128];
    __shared__ float h2[64];
    __shared__ float mixed[16];

    const float* gm = g_gmax + b * Mrows;
#pragma unroll
    for (int s = 0; s < 4; s++) sh_h[tid + s * 64] = gm[tid + s * 64];
    sh_g[tid] = gm[256 + tid];
    __syncthreads();

    if (tid < 4) {
        float s = gate_lb[tid];
        for (int h = 0; h < 64; h++) s += sh_g[h] * gate_lw[tid * 64 + h];
        gate_o[tid] = s;
    }
    __syncthreads();
    if (tid == 0) {
        float mx = fmaxf(fmaxf(gate_o[0], gate_o[1]), fmaxf(gate_o[2], gate_o[3]));
        float e0 = expf(gate_o[0] - mx), e1 = expf(gate_o[1] - mx);
        float e2 = expf(gate_o[2] - mx), e3 = expf(gate_o[3] - mx);
        float inv = 1.f / (e0 + e1 + e2 + e3);
        gate_o[0] = e0 * inv; gate_o[1] = e1 * inv;
        gate_o[2] = e2 * inv; gate_o[3] = e3 * inv;
    }
    __syncthreads();

    for (int r = tid; r < 128; r += 64) {
        int e = r >> 5;
        float s = exp_b1[r];
        const float* w = exp_w1 + (size_t)r * 64;
        const float* hv = sh_h + e * 64;
        for (int c = 0; c < 64; c++) s += hv[c] * w[c];
        h1[r] = fmaxf(s, 0.f);
    }
    __syncthreads();

    {
        int e = tid >> 4;
        float s = exp_b2[tid];
        const float* w = exp_w2 + (size_t)tid * 32;
        const float* hv = h1 + e * 32;
        for (int o = 0; o < 32; o++) s += hv[o] * w[o];
        h2[tid] = fmaxf(s, 0.f);
    }
    __syncthreads();

    if (tid < 16) {
        float s = 0.f;
        for (int e = 0; e < En; e++) s += gate_o[e] * h2[e * 16 + tid];
        mixed[tid] = s;
    }
    __syncthreads();

    if (tid == 0) {
        float lg[OUTn];
        float mx = -1e30f;
        for (int k = 0; k < OUTn; k++) {
            float s = fc_b[k];
            for (int f = 0; f < 16; f++) s += mixed[f] * fc_w[k * 16 + f];
            lg[k] = s;
            mx = fmaxf(mx, s);
        }
        float se = 0.f;
        for (int k = 0; k < OUTn; k++) se += expf(lg[k] - mx);
        float lse = mx + logf(se);
        for (int k = 0; k < OUTn; k++) out[b * OUTn + k] = lg[k] - lse;
        if (out_size >= B_ * OUTn + B_ * En) {
            for (int e = 0; e < En; e++) out[B_ * OUTn + b * En + e] = gate_o[e];
        }
    }
}

// ---------------------------------------------------------------------------
extern "C" void kernel_launch(void* const* d_in, const int* in_sizes, int n_in,
                              void* d_out, int out_size) {
    const float* fs      = (const float*)d_in[0];
    const float* fp      = (const float*)d_in[1];
    const float* gate_cw = (const float*)d_in[2];
    const float* gate_cb = (const float*)d_in[3];
    const float* gate_lw = (const float*)d_in[4];
    const float* gate_lb = (const float*)d_in[5];
    const float* exp_cw  = (const float*)d_in[6];
    const float* exp_cb  = (const float*)d_in[7];
    const float* exp_w1  = (const float*)d_in[8];
    const float* exp_b1  = (const float*)d_in[9];
    const float* exp_w2  = (const float*)d_in[10];
    const float* exp_b2  = (const float*)d_in[11];
    const float* fc_w    = (const float*)d_in[12];
    const float* fc_b    = (const float*)d_in[13];
    float* out = (float*)d_out;

    // Opt-in >48KB dynamic smem. Idempotent; first (uncaptured) call makes it
    // stick process-wide, so a capture-time failure is harmless.
    cudaFuncSetAttribute(conv_gemm,
                         cudaFuncAttributeMaxDynamicSharedMemorySize, DYN_SMEM);

    {
        int total = Mrows * Kdim;
        prep_w<<<(total + 255) / 256, 256>>>(gate_cw, gate_cb, exp_cw, exp_cb);
    }
    {
        int total = B_ * Lnum * 32;
        prep_x<<<(total + 255) / 256, 256>>>(fs, fp);
    }
    conv_gemm<<<dim3(5, 128), 256, DYN_SMEM>>>();
    tail_kernel<<<B_, 64>>>(gate_lw, gate_lb, exp_w1, exp_b1, exp_w2, exp_b2,
                            fc_w, fc_b, out, out_size);
}